// round 7
// baseline (speedup 1.0000x reference)
#include <cuda_runtime.h>
#include <cuda_fp16.h>
#include <math.h>

#define BB 8
#define TT 2048
#define DUx 512
#define DMx 512
#define DAx 256
#define DFx 12
#define NSTAGE 4
#define EPSV 1e-6f
#define INV_SCALE (1.0f/16.0f)

// ---------------- scratch (device globals; no allocation) ----------------
__device__ float g_usq[BB*TT];
__device__ float g_sbias[BB*TT];
__device__ float g_base[BB*TT];    // u·qk/16 + sbias (pre sp/temp)
__device__ float g_y[BB*TT];       // y_final only
__device__ float g_overlap[BB*TT];
__device__ float g_sp[BB*TT];      // sim @ prev (accumulated)
__device__ float g_yu[BB*DUx];     // y @ u  (raw centroid)
__device__ float g_x[BB*DUx];      // GRU input z part (stats built in gru)
__device__ float g_memA[BB*DMx];
__device__ float g_memB[BB*DMx];
__device__ float g_qk[BB*DUx];     // M @ mem
__device__ float g_stat[BB*8];     // [ys, coverage, entropy, wsq, spread_acc, csq]
__device__ float g_M[DUx*DMx];     // Wk^T @ Wq

// fp16 compressed copies (written once, read many)
__device__ __half g_simh[(size_t)BB*TT*TT];   // 67 MB
__device__ __half g_uh[(size_t)BB*TT*DUx];    // 17 MB

// ---------------- reduction helpers ----------------
__device__ __forceinline__ float warpSum(float v){
    #pragma unroll
    for (int o = 16; o; o >>= 1) v += __shfl_xor_sync(0xffffffffu, v, o);
    return v;
}
__device__ __forceinline__ float warpMax(float v){
    #pragma unroll
    for (int o = 16; o; o >>= 1) v = fmaxf(v, __shfl_xor_sync(0xffffffffu, v, o));
    return v;
}
__device__ __forceinline__ float blockSum(float v, float* sh){
    int lane = threadIdx.x & 31, w = threadIdx.x >> 5;
    int nw = (blockDim.x + 31) >> 5;
    v = warpSum(v);
    if (lane == 0) sh[w] = v;
    __syncthreads();
    if (w == 0){
        float x = (lane < nw) ? sh[lane] : 0.f;
        x = warpSum(x);
        if (lane == 0) sh[0] = x;
    }
    __syncthreads();
    float r = sh[0];
    __syncthreads();
    return r;
}
__device__ __forceinline__ float blockMax(float v, float* sh){
    int lane = threadIdx.x & 31, w = threadIdx.x >> 5;
    int nw = (blockDim.x + 31) >> 5;
    v = warpMax(v);
    if (lane == 0) sh[w] = v;
    __syncthreads();
    if (w == 0){
        float x = (lane < nw) ? sh[lane] : -INFINITY;
        x = warpMax(x);
        if (lane == 0) sh[0] = x;
    }
    __syncthreads();
    float r = sh[0];
    __syncthreads();
    return r;
}

// ---------------- sim fp32 -> fp16 (standalone, overlapped with prologue) ----------------
__global__ void k_conv(const float* __restrict__ sim){
    size_t i = (size_t)blockIdx.x * blockDim.x + threadIdx.x;  // one int4 (8 halves)
    const float4* in = (const float4*)sim;
    float4 f0 = in[2*i], f1 = in[2*i+1];
    __half2 h0 = __floats2half2_rn(f0.x, f0.y);
    __half2 h1 = __floats2half2_rn(f0.z, f0.w);
    __half2 h2 = __floats2half2_rn(f1.x, f1.y);
    __half2 h3 = __floats2half2_rn(f1.z, f1.w);
    int4 o;
    o.x = *(int*)&h0; o.y = *(int*)&h1; o.z = *(int*)&h2; o.w = *(int*)&h3;
    ((int4*)g_simh)[i] = o;
}

// ---------------- init: zero sp, copy memory0 ----------------
__global__ void k_init(const float* __restrict__ mem0){
    int i = blockIdx.x * blockDim.x + threadIdx.x;
    if (i < BB*TT) g_sp[i] = 0.f;
    if (i < BB*DMx) g_memA[i] = mem0[i];
}

// ---------------- M = Wk^T @ Wq  (512x512, K=256), tiled ----------------
__global__ void k_Mpre(const float* __restrict__ Wk, const float* __restrict__ Wq){
    int bm = blockIdx.x & 15, bd = blockIdx.x >> 4;
    int d0 = bd*32, m0 = bm*32;
    __shared__ float sA[32*32];
    __shared__ float sB[32*32];
    float acc[4] = {0.f, 0.f, 0.f, 0.f};
    int tx = threadIdx.x & 31, ty = threadIdx.x >> 5;
    for (int a0 = 0; a0 < DAx; a0 += 32){
        __syncthreads();
        for (int i = threadIdx.x; i < 1024; i += 256){
            int ar = i >> 5, col = i & 31;
            sA[i] = Wk[(size_t)(a0+ar)*DUx + d0 + col];
            sB[i] = Wq[(size_t)(a0+ar)*DMx + m0 + col];
        }
        __syncthreads();
        #pragma unroll
        for (int aa = 0; aa < 32; aa++){
            float bv = sB[aa*32 + tx];
            #pragma unroll
            for (int r = 0; r < 4; r++)
                acc[r] += sA[aa*32 + ty + r*8] * bv;
        }
    }
    #pragma unroll
    for (int r = 0; r < 4; r++)
        g_M[(size_t)(d0 + ty + r*8)*DMx + m0 + tx] = acc[r];
}

// ---------------- precompute: usq[b,t], sbias[b,t], u -> fp16 ----------------
__global__ void k_pre(const float* __restrict__ u, const float* __restrict__ sf,
                      const float* __restrict__ w1, const float* __restrict__ b1,
                      const float* __restrict__ w2, const float* __restrict__ b2){
    int b  = blockIdx.x >> 8;
    int t0 = (blockIdx.x & 255) * 8;
    int w = threadIdx.x >> 5, lane = threadIdx.x & 31;
    int t = t0 + w, bt = b*TT + t;
    const float4* up = (const float4*)(u + (size_t)bt * DUx);
    int4* uo = (int4*)(g_uh + (size_t)bt * DUx);
    float acc = 0.f;
    #pragma unroll
    for (int c = 0; c < 2; c++){
        int idx = c*32 + lane;
        float4 f0 = up[2*idx], f1 = up[2*idx+1];
        acc += f0.x*f0.x + f0.y*f0.y + f0.z*f0.z + f0.w*f0.w
             + f1.x*f1.x + f1.y*f1.y + f1.z*f1.z + f1.w*f1.w;
        __half2 h0 = __floats2half2_rn(f0.x, f0.y);
        __half2 h1 = __floats2half2_rn(f0.z, f0.w);
        __half2 h2 = __floats2half2_rn(f1.x, f1.y);
        __half2 h3 = __floats2half2_rn(f1.z, f1.w);
        int4 o;
        o.x = *(int*)&h0; o.y = *(int*)&h1; o.z = *(int*)&h2; o.w = *(int*)&h3;
        uo[idx] = o;
    }
    acc = warpSum(acc);
    float d0 = sf[bt*DFx + 8], d1 = sf[bt*DFx + 9], d2 = sf[bt*DFx + 10];
    float sb = 0.f;
    #pragma unroll
    for (int k = 0; k < 8; k++){
        int a = lane + k*32;
        float h = w1[a*3+0]*d0 + w1[a*3+1]*d1 + w1[a*3+2]*d2 + b1[a];
        h = 0.5f * h * (1.f + erff(h * 0.70710678118654752f));
        sb += h * w2[a];
    }
    sb = warpSum(sb);
    if (lane == 0){ g_usq[bt] = acc; g_sbias[bt] = sb + b2[0]; }
}

// ---------------- qk: each warp = one M-row dotted with all 8 batch mems ----------------
__global__ void k_qk(int inB){   // grid 64, block 256
    const float* mem_in = inB ? g_memB : g_memA;
    __shared__ float4 s_m4[BB*DMx/4];   // 16 KB: all 8 mems
    for (int i = threadIdx.x; i < BB*DMx/4; i += 256)
        s_m4[i] = ((const float4*)mem_in)[i];
    __syncthreads();
    int w = threadIdx.x >> 5, lane = threadIdx.x & 31;
    int d = blockIdx.x * 8 + w;
    const float4* row = (const float4*)(g_M + (size_t)d * DMx);
    float4 r[4];
    #pragma unroll
    for (int c = 0; c < 4; c++) r[c] = row[c*32 + lane];
    float acc[BB];
    #pragma unroll
    for (int b = 0; b < BB; b++){
        float a = 0.f;
        #pragma unroll
        for (int c = 0; c < 4; c++){
            float4 m4 = s_m4[b*128 + c*32 + lane];
            a += r[c].x*m4.x + r[c].y*m4.y + r[c].z*m4.z + r[c].w*m4.w;
        }
        acc[b] = warpSum(a);
    }
    if (lane == 0){
        #pragma unroll
        for (int b = 0; b < BB; b++) g_qk[b*DUx + d] = acc[b];
    }
}

// ---------------- base[b,t] = u·qk/16 + sbias ----------------
__global__ void k_scores(){
    int b  = blockIdx.x >> 8;
    int t0 = (blockIdx.x & 255) * 8;
    __shared__ float2 s_qk2[DUx/2];
    for (int i = threadIdx.x; i < DUx/2; i += blockDim.x)
        s_qk2[i] = ((const float2*)(g_qk + b*DUx))[i];
    __syncthreads();
    int w = threadIdx.x >> 5, lane = threadIdx.x & 31;
    int t = t0 + w, bt = b*TT + t;
    const int4* rowh = (const int4*)(g_uh + (size_t)bt * DUx);
    float acc = 0.f;
    #pragma unroll
    for (int c = 0; c < 2; c++){
        int idx = c*32 + lane;
        int4 h = rowh[idx];
        __half2* hp = (__half2*)&h;
        #pragma unroll
        for (int j = 0; j < 4; j++){
            float2 uv = __half22float2(hp[j]);
            float2 qv = s_qk2[idx*4 + j];
            acc += uv.x*qv.x + uv.y*qv.y;
        }
    }
    acc = warpSum(acc);
    if (lane == 0) g_base[bt] = acc * INV_SCALE + g_sbias[bt];
}

// ---------------- fused: softmax(base-sp)/temp  ->  overlap = sim @ y_pre ----------------
__global__ void k_simmv_ov(const float* __restrict__ lt){
    int b  = blockIdx.x >> 8;
    int t0 = (blockIdx.x & 255) * 8;
    __shared__ float2 s_y2[TT/2];   // holds exp(l-m)
    __shared__ float sh[32];
    float temp = fminf(fmaxf(expf(lt[0]), 0.1f), 10.f);
    float invT = 1.f / temp;
    float lv[8];
    float mloc = -INFINITY;
    #pragma unroll
    for (int k = 0; k < 8; k++){
        int j = threadIdx.x + k*256;
        lv[k] = (g_base[b*TT+j] - g_sp[b*TT+j]) * invT;
        mloc = fmaxf(mloc, lv[k]);
    }
    float m = blockMax(mloc, sh);
    float se = 0.f;
    #pragma unroll
    for (int k = 0; k < 8; k++){
        int j = threadIdx.x + k*256;
        float e = expf(lv[k] - m);
        ((float*)s_y2)[j] = e;
        se += e;
    }
    float S = blockSum(se, sh);      // blockSum syncs -> s_y2 stores visible
    float invS = 1.f / S;
    int w = threadIdx.x >> 5, lane = threadIdx.x & 31;
    int t = t0 + w, bt = b*TT + t;
    const int4* row = (const int4*)(g_simh + (size_t)bt * TT);
    float acc = 0.f;
    #pragma unroll
    for (int c = 0; c < 8; c++){
        int idx = c*32 + lane;
        int4 h = row[idx];
        __half2* hp = (__half2*)&h;
        #pragma unroll
        for (int j = 0; j < 4; j++){
            float2 sv = __half22float2(hp[j]);
            float2 yv = s_y2[idx*4 + j];
            acc += sv.x*yv.x + sv.y*yv.y;
        }
    }
    acc = warpSum(acc);
    if (lane == 0) g_overlap[bt] = acc * invS;
}

// ---------------- sp += sim @ y_final (side stream) ----------------
__global__ void k_simmv_sp(){
    int b  = blockIdx.x >> 8;
    int t0 = (blockIdx.x & 255) * 8;
    __shared__ float2 s_y2[TT/2];
    for (int i = threadIdx.x; i < TT/2; i += blockDim.x)
        s_y2[i] = ((const float2*)(g_y + b*TT))[i];
    __syncthreads();
    int w = threadIdx.x >> 5, lane = threadIdx.x & 31;
    int t = t0 + w, bt = b*TT + t;
    const int4* row = (const int4*)(g_simh + (size_t)bt * TT);
    float acc = 0.f;
    #pragma unroll
    for (int c = 0; c < 8; c++){
        int idx = c*32 + lane;
        int4 h = row[idx];
        __half2* hp = (__half2*)&h;
        #pragma unroll
        for (int j = 0; j < 4; j++){
            float2 sv = __half22float2(hp[j]);
            float2 yv = s_y2[idx*4 + j];
            acc += sv.x*yv.x + sv.y*yv.y;
        }
    }
    acc = warpSum(acc);
    if (lane == 0) g_sp[bt] += acc;
}

// ---------------- penalty + second softmax + scalar stats ----------------
__global__ void k_penalty(const float* __restrict__ lt){
    int b = blockIdx.x;
    int i0 = b*TT + threadIdx.x, i1 = i0 + 1024;
    __shared__ float sh[32];
    float temp = fminf(fmaxf(expf(lt[0]), 0.1f), 10.f);
    float invT = 1.f / temp;
    float o0 = g_overlap[i0], o1 = g_overlap[i1];
    float mo = blockMax(fmaxf(o0, o1), sh);
    mo = fmaxf(mo, EPSV);
    float invmo = 1.f / mo;
    float l0 = (g_base[i0] - g_sp[i0]) * invT - o0*invmo;
    float l1 = (g_base[i1] - g_sp[i1]) * invT - o1*invmo;
    float m = blockMax(fmaxf(l0, l1), sh);
    float e0 = expf(l0 - m), e1 = expf(l1 - m);
    float S = blockSum(e0 + e1, sh);
    float invS = 1.f / S;
    float y0 = e0*invS, y1 = e1*invS;
    g_y[i0] = y0; g_y[i1] = y1;
    float ysum = blockSum(y0 + y1, sh);
    float ys = fmaxf(ysum, EPSV);
    float invys = 1.f / ys;
    float yn0 = y0*invys, yn1 = y1*invys;
    float ent = blockSum(-yn0*logf(fmaxf(yn0, EPSV)) - yn1*logf(fmaxf(yn1, EPSV)), sh);
    float wsq = blockSum(y0*g_usq[i0] + y1*g_usq[i1], sh);
    if (threadIdx.x == 0){
        g_stat[b*8+0] = ys;
        g_stat[b*8+1] = ysum * (1.f/(float)TT);
        g_stat[b*8+2] = ent;
        g_stat[b*8+3] = wsq;
        g_stat[b*8+4] = 0.f;
    }
    if (threadIdx.x < DUx) g_yu[b*DUx + threadIdx.x] = 0.f;
}

// ---------------- yu = y @ u (fp16 u; partial sums + atomics) ----------------
__global__ void k_yu(){
    int b  = blockIdx.x >> 6;
    int t0 = (blockIdx.x & 63) * 32;
    __shared__ float s_y[32];
    if (threadIdx.x < 32) s_y[threadIdx.x] = g_y[b*TT + t0 + threadIdx.x];
    __syncthreads();
    float ax = 0.f, ay = 0.f;
    const __half2* up = (const __half2*)(g_uh + ((size_t)b*TT + t0) * DUx);
    #pragma unroll 8
    for (int i = 0; i < 32; i++){
        float yv = s_y[i];
        float2 v = __half22float2(up[i*256 + threadIdx.x]);
        ax += yv * v.x; ay += yv * v.y;
    }
    atomicAdd(&g_yu[b*DUx + 2*threadIdx.x],     ax);
    atomicAdd(&g_yu[b*DUx + 2*threadIdx.x + 1], ay);
}

// ---------------- spread + csq (side stream, parallel with zx) ----------------
__global__ void k_dist(){
    int b  = blockIdx.x >> 8;
    int t0 = (blockIdx.x & 255) * 8;
    __shared__ float2 s_cen2[DUx/2];
    __shared__ float sh[32];
    float ys = g_stat[b*8+0];
    float invys = 1.f / ys;
    for (int i = threadIdx.x; i < DUx/2; i += 256){
        float2 c2 = ((const float2*)(g_yu + b*DUx))[i];
        s_cen2[i] = make_float2(c2.x*invys, c2.y*invys);
    }
    __syncthreads();
    int w = threadIdx.x >> 5, lane = threadIdx.x & 31;
    int t = t0 + w, bt = b*TT + t;
    const int4* rowh = (const int4*)(g_uh + (size_t)bt * DUx);
    float acc = 0.f;
    #pragma unroll
    for (int c = 0; c < 2; c++){
        int idx = c*32 + lane;
        int4 h = rowh[idx];
        __half2* hp = (__half2*)&h;
        #pragma unroll
        for (int j = 0; j < 4; j++){
            float2 uv = __half22float2(hp[j]);
            float2 cn = s_cen2[idx*4 + j];
            float dx = uv.x - cn.x, dy = uv.y - cn.y;
            acc += dx*dx + dy*dy;
        }
    }
    acc = warpSum(acc);
    float part = (lane == 0) ? g_y[bt] * sqrtf(acc) : 0.f;
    float tot = blockSum(part, sh);
    if (threadIdx.x == 0) atomicAdd(&g_stat[b*8+4], tot);
    if ((blockIdx.x & 255) == 0){
        float2 c2 = s_cen2[threadIdx.x];
        float v = blockSum(c2.x*c2.x + c2.y*c2.y, sh);
        if (threadIdx.x == 0) g_stat[b*8+5] = v * ys * ys;   // csq = sum(yu^2)
    }
}

// ---------------- z = Wv @ yu ; write out + g_x[0..511] ----------------
__global__ void k_zx(const float* __restrict__ Wv, float* __restrict__ out, int stage){
    int b = blockIdx.x >> 3;
    int c = blockIdx.x & 7;
    __shared__ float4 s_yu4[DUx/4];
    for (int i = threadIdx.x; i < DUx/4; i += 256)
        s_yu4[i] = ((const float4*)(g_yu + b*DUx))[i];
    __syncthreads();
    int w = threadIdx.x >> 5, lane = threadIdx.x & 31;
    #pragma unroll
    for (int j = 0; j < 8; j++){
        int d = c*64 + w*8 + j;
        const float4* row = (const float4*)(Wv + (size_t)d * DUx);
        float acc = 0.f;
        #pragma unroll
        for (int cc = 0; cc < 4; cc++){
            int idx = cc*32 + lane;
            float4 a = row[idx], yv = s_yu4[idx];
            acc += a.x*yv.x + a.y*yv.y + a.z*yv.z + a.w*yv.w;
        }
        acc = warpSum(acc);
        if (lane == 0){
            out[((size_t)b*NSTAGE + stage)*DUx + d] = acc;
            g_x[b*DUx + d] = acc;
        }
    }
}

// ---------------- GRU cell update; stats built inline ----------------
__global__ void k_gru(const float* __restrict__ W_ih, const float* __restrict__ b_ih,
                      const float* __restrict__ W_hh, const float* __restrict__ b_hh,
                      int inB){
    const float* mem_in  = inB ? g_memB : g_memA;
    float*       mem_out = inB ? g_memA : g_memB;
    int b = blockIdx.x >> 3;
    int c = blockIdx.x & 7;
    __shared__ float4 s_x4[129];   // 516 floats
    __shared__ float4 s_m4[DMx/4];
    float* s_x = (float*)s_x4; float* s_m = (float*)s_m4;
    for (int i = threadIdx.x; i < DUx; i += 256) s_x[i] = g_x[b*DUx + i];
    for (int i = threadIdx.x; i < DMx; i += 256) s_m[i] = mem_in[b*DMx + i];
    if (threadIdx.x == 0){
        float ys = g_stat[b*8+0];
        s_x[512] = g_stat[b*8+1];                                           // coverage
        s_x[513] = g_stat[b*8+2];                                           // entropy
        s_x[514] = g_stat[b*8+4] / ys;                                      // spread
        s_x[515] = 2.f*(ys*g_stat[b*8+3] - g_stat[b*8+5]) / fmaxf(ys*ys, EPSV); // compact
    }
    __syncthreads();
    int w = threadIdx.x >> 5, lane = threadIdx.x & 31;
    for (int jj = 0; jj < 8; jj++){
        int j = c*64 + w*8 + jj;
        float gi[3], gh[3];
        #pragma unroll
        for (int g = 0; g < 3; g++){
            int r = j + g*DMx;
            const float4* wi = (const float4*)(W_ih + (size_t)r * 516);
            float acc = 0.f;
            #pragma unroll
            for (int cc = 0; cc < 4; cc++){
                int idx = cc*32 + lane;
                float4 a = wi[idx], xx = s_x4[idx];
                acc += a.x*xx.x + a.y*xx.y + a.z*xx.z + a.w*xx.w;
            }
            if (lane == 0){
                float4 a = wi[128], xx = s_x4[128];
                acc += a.x*xx.x + a.y*xx.y + a.z*xx.z + a.w*xx.w;
            }
            acc = warpSum(acc);
            gi[g] = acc + b_ih[r];

            const float4* wh = (const float4*)(W_hh + (size_t)r * DMx);
            float acch = 0.f;
            #pragma unroll
            for (int cc = 0; cc < 4; cc++){
                int idx = cc*32 + lane;
                float4 a = wh[idx], mm = s_m4[idx];
                acch += a.x*mm.x + a.y*mm.y + a.z*mm.z + a.w*mm.w;
            }
            acch = warpSum(acch);
            gh[g] = acch + b_hh[r];
        }
        if (lane == 0){
            float rg = 1.f / (1.f + expf(-(gi[0] + gh[0])));
            float zg = 1.f / (1.f + expf(-(gi[1] + gh[1])));
            float ng = tanhf(gi[2] + rg * gh[2]);
            mem_out[b*DMx + j] = (1.f - zg) * ng + zg * s_m[j];
        }
    }
}

// ---------------- launch ----------------
extern "C" void kernel_launch(void* const* d_in, const int* in_sizes, int n_in,
                              void* d_out, int out_size){
    const float* u    = (const float*)d_in[0];
    const float* sf   = (const float*)d_in[1];
    const float* sim  = (const float*)d_in[2];
    const float* mem0 = (const float*)d_in[3];
    const float* Wq   = (const float*)d_in[4];
    const float* Wk   = (const float*)d_in[5];
    const float* Wv   = (const float*)d_in[6];
    const float* sbw1 = (const float*)d_in[7];
    const float* sbb1 = (const float*)d_in[8];
    const float* sbw2 = (const float*)d_in[9];
    const float* sbb2 = (const float*)d_in[10];
    const float* lt   = (const float*)d_in[11];
    const float* Wih  = (const float*)d_in[12];
    const float* bih  = (const float*)d_in[13];
    const float* Whh  = (const float*)d_in[14];
    const float* bhh  = (const float*)d_in[15];
    float* out = (float*)d_out;

    static cudaStream_t s2 = nullptr, s3 = nullptr;
    static cudaEvent_t evR, evP, evF[3], evJ[3], evY[4], evD[4];
    if (s2 == nullptr){
        cudaStreamCreateWithFlags(&s2, cudaStreamNonBlocking);
        cudaStreamCreateWithFlags(&s3, cudaStreamNonBlocking);
        cudaEventCreateWithFlags(&evR, cudaEventDisableTiming);
        cudaEventCreateWithFlags(&evP, cudaEventDisableTiming);
        for (int i = 0; i < 3; i++){
            cudaEventCreateWithFlags(&evF[i], cudaEventDisableTiming);
            cudaEventCreateWithFlags(&evJ[i], cudaEventDisableTiming);
        }
        for (int i = 0; i < 4; i++){
            cudaEventCreateWithFlags(&evY[i], cudaEventDisableTiming);
            cudaEventCreateWithFlags(&evD[i], cudaEventDisableTiming);
        }
    }

    // fork prologue chain to s2; sim conversion runs on main concurrently
    cudaEventRecord(evR, 0);
    cudaStreamWaitEvent(s2, evR, 0);
    k_conv<<<16384, 256>>>(sim);
    k_init<<<64, 256, 0, s2>>>(mem0);
    k_Mpre<<<256, 256, 0, s2>>>(Wk, Wq);
    k_pre<<<BB*TT/8, 256, 0, s2>>>(u, sf, sbw1, sbb1, sbw2, sbb2);
    k_qk<<<64, 256, 0, s2>>>(0);
    k_scores<<<BB*TT/8, 256, 0, s2>>>();
    cudaEventRecord(evP, s2);
    cudaStreamWaitEvent(0, evP, 0);

    for (int s = 0; s < NSTAGE; s++){
        if (s > 0) cudaStreamWaitEvent(0, evJ[s-1], 0);   // sp_{s} ready
        k_simmv_ov<<<BB*TT/8, 256>>>(lt);                 // softmax + overlap fused
        k_penalty<<<BB, 1024>>>(lt);                      // y_final + stats
        if (s < NSTAGE - 1){
            cudaEventRecord(evF[s], 0);
            cudaStreamWaitEvent(s2, evF[s], 0);
            k_simmv_sp<<<BB*TT/8, 256, 0, s2>>>();        // sp += sim @ y_final (hidden)
            cudaEventRecord(evJ[s], s2);
        }
        k_yu<<<BB*64, 256>>>();
        cudaEventRecord(evY[s], 0);
        cudaStreamWaitEvent(s3, evY[s], 0);
        k_dist<<<BB*TT/8, 256, 0, s3>>>();                // spread + csq, parallel w/ zx
        cudaEventRecord(evD[s], s3);
        k_zx<<<BB*8, 256>>>(Wv, out, s);
        cudaStreamWaitEvent(0, evD[s], 0);
        k_gru<<<BB*8, 256>>>(Wih, bih, Whh, bhh, s & 1);
        if (s < NSTAGE - 1){
            k_qk<<<64, 256>>>((s+1) & 1);
            k_scores<<<BB*TT/8, 256>>>();
        }
    }
}